// round 3
// baseline (speedup 1.0000x reference)
#include <cuda_runtime.h>
#include <math.h>

// ---------------- problem constants ----------------
#define B_   64
#define C_   384
#define HW_  256            // n = H*W
#define MTOT (B_*HW_)       // 16384
#define HEADS 8
#define DHEAD 32
#define INNER (HEADS*DHEAD) // 256
#define HID   (4*C_)        // 1536

// ---------------- device scratch (allocation-free rule) ----------------
__device__ float g_t  [MTOT*C_];     // t  [B,n,C]
__device__ float g_a  [MTOT*C_];     // LN1(t)  (reused later as final y)
__device__ float g_f  [MTOT*C_];     // LN2(t)
__device__ float g_qkv[MTOT*3*INNER];
__device__ float g_o  [MTOT*INNER];
__device__ float g_s1 [MTOT*C_];     // t + attn_out
__device__ float g_g  [MTOT*HID];    // gelu(ff1)

// ---------------- fused transpose + dual LayerNorm ----------------
__global__ void ln_kernel(const float* __restrict__ x,
                          const float* __restrict__ g1, const float* __restrict__ b1,
                          const float* __restrict__ g2, const float* __restrict__ b2,
                          float* __restrict__ t, float* __restrict__ a, float* __restrict__ f)
{
    int row = blockIdx.x;            // b*n + p
    int b   = row >> 8;
    int p   = row & 255;
    int c   = threadIdx.x;           // 0..383

    float v = x[((size_t)b*C_ + c)*HW_ + p];

    __shared__ float red[12];
    __shared__ float s_mean, s_var;

    float s = v;
    #pragma unroll
    for (int o = 16; o; o >>= 1) s += __shfl_down_sync(0xffffffffu, s, o);
    if ((c & 31) == 0) red[c >> 5] = s;
    __syncthreads();
    if (c < 32) {
        float z = (c < 12) ? red[c] : 0.f;
        #pragma unroll
        for (int o = 16; o; o >>= 1) z += __shfl_down_sync(0xffffffffu, z, o);
        if (c == 0) s_mean = z * (1.f/384.f);
    }
    __syncthreads();
    float mean = s_mean;
    float d = v - mean;

    float sq = d*d;
    #pragma unroll
    for (int o = 16; o; o >>= 1) sq += __shfl_down_sync(0xffffffffu, sq, o);
    __syncthreads();
    if ((c & 31) == 0) red[c >> 5] = sq;
    __syncthreads();
    if (c < 32) {
        float z = (c < 12) ? red[c] : 0.f;
        #pragma unroll
        for (int o = 16; o; o >>= 1) z += __shfl_down_sync(0xffffffffu, z, o);
        if (c == 0) s_var = z * (1.f/384.f);
    }
    __syncthreads();
    float rstd = rsqrtf(s_var + 1e-5f);

    size_t oidx = (size_t)row*C_ + c;
    t[oidx] = v;
    float nrm = d * rstd;
    a[oidx] = nrm * g1[c] + b1[c];
    f[oidx] = nrm * g2[c] + b2[c];
}

// ---------------- tf32 tensor-core GEMM ----------------
// C[M,N] = A[M,K] @ B[K,N]  (+bias[col]) (gelu) (+add[row,col])
// BM=128 BN=64 BK=32, 256 threads (8 warps 4x2), warp tile 32x32 via m16n8k8.
// Double-buffered SMEM in exact mma fragment layout -> conflict-free LDS,
// one __syncthreads per k-tile, 2 CTAs/SM.
__device__ __forceinline__ unsigned f2tf(float x) {
    unsigned u;
    asm("cvt.rna.tf32.f32 %0, %1;" : "=r"(u) : "f"(x));
    return u;
}

__global__ __launch_bounds__(256, 2)
void tgemm_kernel(const float* __restrict__ A, const float* __restrict__ Bm,
                  float* __restrict__ C, int M, int N, int K,
                  const float* __restrict__ bias, const float* __restrict__ add,
                  int do_gelu)
{
    // fragment-layout smem, double buffered
    __shared__ __align__(16) unsigned AF[2][32*32*4];  // 2 x 16KB
    __shared__ __align__(16) unsigned BF[2][32*32*2];  // 2 x 8KB

    const int tid  = threadIdx.x;
    const int warp = tid >> 5;
    const int lane = tid & 31;
    const int g    = lane >> 2;   // group 0..7
    const int t4   = lane & 3;    // 0..3

    const int brow = blockIdx.y * 128;
    const int bcol = blockIdx.x * 64;

    const int wr = warp & 3;      // warp row (rows wr*32)
    const int wc = warp >> 2;     // warp col (cols wc*32)

    float acc[2][4][4];
    #pragma unroll
    for (int mi = 0; mi < 2; mi++)
        #pragma unroll
        for (int ni = 0; ni < 4; ni++)
            #pragma unroll
            for (int e = 0; e < 4; e++) acc[mi][ni][e] = 0.f;

    float pa[4][4];
    float pb[4][2];

    auto load_regs = [&](int k0) {
        #pragma unroll
        for (int q = 0; q < 4; q++) {
            int idx = warp*4 + q;              // 0..31
            int ch  = idx >> 3;                // k-chunk 0..3
            int mt  = idx & 7;                 // mtile 0..7
            int r0  = brow + mt*16 + g;
            int kk  = k0 + ch*8 + t4;
            pa[q][0] = A[(size_t)r0*K + kk];
            pa[q][1] = A[(size_t)(r0+8)*K + kk];
            pa[q][2] = A[(size_t)r0*K + kk + 4];
            pa[q][3] = A[(size_t)(r0+8)*K + kk + 4];
        }
        #pragma unroll
        for (int q = 0; q < 4; q++) {
            int idx = warp*4 + q;              // 0..31
            int ch  = idx >> 3;                // k-chunk 0..3
            int nt  = idx & 7;                 // ntile 0..7
            int col = bcol + nt*8 + g;
            int kk  = k0 + ch*8 + t4;
            pb[q][0] = Bm[(size_t)kk*N + col];
            pb[q][1] = Bm[(size_t)(kk+4)*N + col];
        }
    };

    auto store_smem = [&](int buf) {
        #pragma unroll
        for (int q = 0; q < 4; q++) {
            int idx = warp*4 + q;
            uint4 u;
            u.x = f2tf(pa[q][0]); u.y = f2tf(pa[q][1]);
            u.z = f2tf(pa[q][2]); u.w = f2tf(pa[q][3]);
            *(uint4*)&AF[buf][(idx*32 + lane)*4] = u;
        }
        #pragma unroll
        for (int q = 0; q < 4; q++) {
            int idx = warp*4 + q;
            uint2 v;
            v.x = f2tf(pb[q][0]); v.y = f2tf(pb[q][1]);
            *(uint2*)&BF[buf][(idx*32 + lane)*2] = v;
        }
    };

    auto compute = [&](int buf) {
        #pragma unroll
        for (int ch = 0; ch < 4; ch++) {
            uint4 a[2];
            #pragma unroll
            for (int mi = 0; mi < 2; mi++)
                a[mi] = *(const uint4*)&AF[buf][((ch*8 + wr*2 + mi)*32 + lane)*4];
            uint2 b[4];
            #pragma unroll
            for (int ni = 0; ni < 4; ni++)
                b[ni] = *(const uint2*)&BF[buf][((ch*8 + wc*4 + ni)*32 + lane)*2];
            #pragma unroll
            for (int mi = 0; mi < 2; mi++)
                #pragma unroll
                for (int ni = 0; ni < 4; ni++) {
                    asm volatile(
                        "mma.sync.aligned.m16n8k8.row.col.f32.tf32.tf32.f32 "
                        "{%0,%1,%2,%3},{%4,%5,%6,%7},{%8,%9},{%0,%1,%2,%3};"
                        : "+f"(acc[mi][ni][0]), "+f"(acc[mi][ni][1]),
                          "+f"(acc[mi][ni][2]), "+f"(acc[mi][ni][3])
                        : "r"(a[mi].x), "r"(a[mi].y), "r"(a[mi].z), "r"(a[mi].w),
                          "r"(b[ni].x), "r"(b[ni].y));
                }
        }
    };

    load_regs(0);
    store_smem(0);
    __syncthreads();

    const int nkt = K >> 5;
    for (int kt = 1; kt < nkt; kt++) {
        load_regs(kt*32);          // LDGs for next tile issue early
        compute((kt-1) & 1);       // mma from current buffer
        store_smem(kt & 1);        // fill other buffer
        __syncthreads();
    }
    compute((nkt-1) & 1);

    // ---- epilogue ----
    #pragma unroll
    for (int mi = 0; mi < 2; mi++) {
        int r0 = brow + wr*32 + mi*16 + g;
        #pragma unroll
        for (int ni = 0; ni < 4; ni++) {
            int col = bcol + wc*32 + ni*8 + 2*t4;
            float v0 = acc[mi][ni][0];
            float v1 = acc[mi][ni][1];
            float v2 = acc[mi][ni][2];
            float v3 = acc[mi][ni][3];
            if (bias) {
                float bz0 = bias[col], bz1 = bias[col+1];
                v0 += bz0; v1 += bz1; v2 += bz0; v3 += bz1;
            }
            if (do_gelu) {
                v0 = 0.5f*v0*(1.f + erff(v0*0.70710678118654752f));
                v1 = 0.5f*v1*(1.f + erff(v1*0.70710678118654752f));
                v2 = 0.5f*v2*(1.f + erff(v2*0.70710678118654752f));
                v3 = 0.5f*v3*(1.f + erff(v3*0.70710678118654752f));
            }
            if (add) {
                float2 a0 = *(const float2*)&add[(size_t)r0*N + col];
                float2 a1 = *(const float2*)&add[(size_t)(r0+8)*N + col];
                v0 += a0.x; v1 += a0.y; v2 += a1.x; v3 += a1.y;
            }
            *(float2*)&C[(size_t)r0*N + col]     = make_float2(v0, v1);
            *(float2*)&C[(size_t)(r0+8)*N + col] = make_float2(v2, v3);
        }
    }
}

// ---------------- attention: one block per (b,h), thread i = query row ----------------
// Scores are tiny (|s| < 1 for these inputs), so softmax is computed without
// max subtraction (shift invariance; no overflow possible here).
#define ATTN_SMEM ((8192 + 8192 + 961) * 4)
__global__ __launch_bounds__(256)
void attn_kernel(const float* __restrict__ qkv, const float* __restrict__ bias_table,
                 float* __restrict__ o)
{
    extern __shared__ float sm[];
    float* ksh = sm;            // [256][32]
    float* vsh = sm + 8192;     // [256][32]
    float* bsh = sm + 16384;    // [961] per-head bias column

    int b = blockIdx.x >> 3;
    int h = blockIdx.x & 7;
    int tid = threadIdx.x;

    const float* base = qkv + (size_t)b * HW_ * (3*INNER);

    for (int l = tid; l < 8192; l += 256) {
        int j = l >> 5, d = l & 31;
        ksh[l] = base[(size_t)j*(3*INNER) + INNER   + h*DHEAD + d];
        vsh[l] = base[(size_t)j*(3*INNER) + 2*INNER + h*DHEAD + d];
    }
    for (int l = tid; l < 961; l += 256) bsh[l] = bias_table[(size_t)l*HEADS + h];
    __syncthreads();

    const int i = tid;
    const float scale = 0.17677669529663688f;   // 1/sqrt(32)
    float4 qv[8];
    const float4* qp = (const float4*)(base + (size_t)i*(3*INNER) + h*DHEAD);
    #pragma unroll
    for (int dd = 0; dd < 8; dd++) {
        float4 q = qp[dd];
        qv[dd] = make_float4(q.x*scale, q.y*scale, q.z*scale, q.w*scale);
    }

    int yi = i >> 4, xi = i & 15;
    float lsum = 0.f;
    float acc[DHEAD];
    #pragma unroll
    for (int d = 0; d < DHEAD; d++) acc[d] = 0.f;

    const float* brow = bsh + (yi + 15)*31 + (xi + 15);
    for (int j = 0; j < HW_; j++) {
        const float4* kr = (const float4*)(ksh + j*DHEAD);
        float s0 = 0.f, s1 = 0.f, s2 = 0.f, s3 = 0.f;
        #pragma unroll
        for (int dd = 0; dd < 8; dd++) {
            float4 kv = kr[dd];
            s0 = fmaf(qv[dd].x, kv.x, s0);
            s1 = fmaf(qv[dd].y, kv.y, s1);
            s2 = fmaf(qv[dd].z, kv.z, s2);
            s3 = fmaf(qv[dd].w, kv.w, s3);
        }
        int yj = j >> 4, xj = j & 15;
        float s = (s0 + s1) + (s2 + s3) + brow[-(yj*31 + xj)];

        float p = __expf(s);
        lsum += p;
        const float4* vr = (const float4*)(vsh + j*DHEAD);
        #pragma unroll
        for (int dd = 0; dd < 8; dd++) {
            float4 vv = vr[dd];
            acc[dd*4+0] = fmaf(p, vv.x, acc[dd*4+0]);
            acc[dd*4+1] = fmaf(p, vv.y, acc[dd*4+1]);
            acc[dd*4+2] = fmaf(p, vv.z, acc[dd*4+2]);
            acc[dd*4+3] = fmaf(p, vv.w, acc[dd*4+3]);
        }
    }

    float inv = 1.f / lsum;
    float* op = o + ((size_t)(b*HW_ + i))*INNER + h*DHEAD;
    #pragma unroll
    for (int d = 0; d < DHEAD; d++) op[d] = acc[d] * inv;
}

// ---------------- output transpose: y[B,n,C] -> out[B,C,H,W] ----------------
__global__ void transpose_out_kernel(const float* __restrict__ y, float* __restrict__ out)
{
    __shared__ float tile[32][33];
    int b  = blockIdx.z;
    int c0 = blockIdx.x * 32;
    int p0 = blockIdx.y * 32;
    const float* yb = y  + (size_t)b * HW_ * C_;
    float*       ob = out + (size_t)b * C_ * HW_;

    for (int i = threadIdx.y; i < 32; i += 8)
        tile[i][threadIdx.x] = yb[(size_t)(p0 + i)*C_ + c0 + threadIdx.x];
    __syncthreads();
    for (int i = threadIdx.y; i < 32; i += 8)
        ob[(size_t)(c0 + i)*HW_ + p0 + threadIdx.x] = tile[threadIdx.x][i];
}

// ---------------- launch ----------------
extern "C" void kernel_launch(void* const* d_in, const int* in_sizes, int n_in,
                              void* d_out, int out_size)
{
    const float* x          = (const float*)d_in[0];
    const float* ln1_g      = (const float*)d_in[1];
    const float* ln1_b      = (const float*)d_in[2];
    const float* w_qkv      = (const float*)d_in[3];
    const float* bias_table = (const float*)d_in[4];
    const float* w_out      = (const float*)d_in[5];
    const float* b_out      = (const float*)d_in[6];
    const float* ln2_g      = (const float*)d_in[7];
    const float* ln2_b      = (const float*)d_in[8];
    const float* w_ff1      = (const float*)d_in[9];
    const float* b_ff1      = (const float*)d_in[10];
    const float* w_ff2      = (const float*)d_in[11];
    const float* b_ff2      = (const float*)d_in[12];

    float *t, *a, *f, *qkv, *o, *s1, *g;
    cudaGetSymbolAddress((void**)&t,   g_t);
    cudaGetSymbolAddress((void**)&a,   g_a);
    cudaGetSymbolAddress((void**)&f,   g_f);
    cudaGetSymbolAddress((void**)&qkv, g_qkv);
    cudaGetSymbolAddress((void**)&o,   g_o);
    cudaGetSymbolAddress((void**)&s1,  g_s1);
    cudaGetSymbolAddress((void**)&g,   g_g);

    cudaFuncSetAttribute(attn_kernel, cudaFuncAttributeMaxDynamicSharedMemorySize, ATTN_SMEM);

    // 1) transpose + LN1 + LN2
    ln_kernel<<<MTOT, 384>>>(x, ln1_g, ln1_b, ln2_g, ln2_b, t, a, f);

    // 2) qkv = a @ w_qkv    [16384,384]x[384,768]
    tgemm_kernel<<<dim3(3*INNER/64, MTOT/128), 256>>>(a, w_qkv, qkv,
        MTOT, 3*INNER, C_, nullptr, nullptr, 0);

    // 3) attention
    attn_kernel<<<B_*HEADS, 256, ATTN_SMEM>>>(qkv, bias_table, o);

    // 4) s1 = t + (o @ w_out + b_out)   [16384,256]x[256,384]
    tgemm_kernel<<<dim3(C_/64, MTOT/128), 256>>>(o, w_out, s1,
        MTOT, C_, INNER, b_out, t, 0);

    // 5) g = gelu(f @ w_ff1 + b_ff1)    [16384,384]x[384,1536]
    tgemm_kernel<<<dim3(HID/64, MTOT/128), 256>>>(f, w_ff1, g,
        MTOT, HID, C_, b_ff1, nullptr, 1);

    // 6) y = s1 + (g @ w_ff2 + b_ff2)   [16384,1536]x[1536,384]  (reuse g_a for y)
    tgemm_kernel<<<dim3(C_/64, MTOT/128), 256>>>(g, w_ff2, a,
        MTOT, C_, HID, b_ff2, s1, 0);

    // 7) out[B,C,H,W] = y transposed
    transpose_out_kernel<<<dim3(C_/32, HW_/32, B_), dim3(32, 8)>>>(a, (float*)d_out);
}

// round 4
// speedup vs baseline: 2.4819x; 2.4819x over previous
#include <cuda_runtime.h>
#include <math.h>

// ---------------- problem constants ----------------
#define B_   64
#define C_   384
#define HW_  256            // n = H*W
#define MTOT (B_*HW_)       // 16384
#define HEADS 8
#define DHEAD 32
#define INNER (HEADS*DHEAD) // 256
#define HID   (4*C_)        // 1536

// ---------------- device scratch (allocation-free rule) ----------------
__device__ float g_t  [MTOT*C_];
__device__ float g_a  [MTOT*C_];
__device__ float g_f  [MTOT*C_];
__device__ float g_qkv[MTOT*3*INNER];
__device__ float g_o  [MTOT*INNER];
__device__ float g_s1 [MTOT*C_];
__device__ float g_g  [MTOT*HID];

// ---------------- fused transpose + dual LayerNorm ----------------
__global__ void ln_kernel(const float* __restrict__ x,
                          const float* __restrict__ g1, const float* __restrict__ b1,
                          const float* __restrict__ g2, const float* __restrict__ b2,
                          float* __restrict__ t, float* __restrict__ a, float* __restrict__ f)
{
    int row = blockIdx.x;
    int b   = row >> 8;
    int p   = row & 255;
    int c   = threadIdx.x;

    float v = x[((size_t)b*C_ + c)*HW_ + p];

    __shared__ float red[12];
    __shared__ float s_mean, s_var;

    float s = v;
    #pragma unroll
    for (int o = 16; o; o >>= 1) s += __shfl_down_sync(0xffffffffu, s, o);
    if ((c & 31) == 0) red[c >> 5] = s;
    __syncthreads();
    if (c < 32) {
        float z = (c < 12) ? red[c] : 0.f;
        #pragma unroll
        for (int o = 16; o; o >>= 1) z += __shfl_down_sync(0xffffffffu, z, o);
        if (c == 0) s_mean = z * (1.f/384.f);
    }
    __syncthreads();
    float mean = s_mean;
    float d = v - mean;

    float sq = d*d;
    #pragma unroll
    for (int o = 16; o; o >>= 1) sq += __shfl_down_sync(0xffffffffu, sq, o);
    __syncthreads();
    if ((c & 31) == 0) red[c >> 5] = sq;
    __syncthreads();
    if (c < 32) {
        float z = (c < 12) ? red[c] : 0.f;
        #pragma unroll
        for (int o = 16; o; o >>= 1) z += __shfl_down_sync(0xffffffffu, z, o);
        if (c == 0) s_var = z * (1.f/384.f);
    }
    __syncthreads();
    float rstd = rsqrtf(s_var + 1e-5f);

    size_t oidx = (size_t)row*C_ + c;
    t[oidx] = v;
    float nrm = d * rstd;
    a[oidx] = nrm * g1[c] + b1[c];
    f[oidx] = nrm * g2[c] + b2[c];
}

// ---------------- tf32 tensor-core GEMM ----------------
// C[M,N] = A[M,K] @ B[K,N]  (+bias[col]) (gelu) (+add[row,col])
// BM=128 BN=128 BK=16, 256 threads (8 warps, 4x2), warp tile 32x64 (m16n8k8).
// cp.async coalesced loads into row-major SMEM; fragment LDS made
// conflict-free by pitch selection (As pitch 20, Bs pitch 136).
__global__ __launch_bounds__(256, 2)
void tgemm_kernel(const float* __restrict__ A, const float* __restrict__ Bm,
                  float* __restrict__ C, int M, int N, int K,
                  const float* __restrict__ bias, const float* __restrict__ add,
                  int do_gelu)
{
    __shared__ float As[2][128][20];    // 20.0 KB
    __shared__ float Bs[2][16][136];    // 17.0 KB

    const int tid  = threadIdx.x;
    const int warp = tid >> 5;
    const int lane = tid & 31;
    const int g    = lane >> 2;
    const int t4   = lane & 3;

    const int brow = blockIdx.y * 128;
    const int bcol = blockIdx.x * 128;

    const int wr = warp & 3;    // rows wr*32
    const int wc = warp >> 2;   // cols wc*64

    float acc[2][8][4];
    #pragma unroll
    for (int mi = 0; mi < 2; mi++)
        #pragma unroll
        for (int ni = 0; ni < 8; ni++)
            #pragma unroll
            for (int e = 0; e < 4; e++) acc[mi][ni][e] = 0.f;

    // A-tile loader: thread handles rows (tid>>2)+{0,64}, float4 col tid&3
    const int a_row = tid >> 2;
    const int a_c4  = (tid & 3) * 4;
    // B-tile loader: thread handles k-rows (tid>>5)+{0,8}, float4 col tid&31
    const int b_kr  = tid >> 5;
    const int b_c4  = (tid & 31) * 4;

    auto issue = [&](int kt, int buf) {
        int k0 = kt * 16;
        #pragma unroll
        for (int q = 0; q < 2; q++) {
            const float* src = &A[(size_t)(brow + a_row + q*64)*K + k0 + a_c4];
            unsigned dst = (unsigned)__cvta_generic_to_shared(&As[buf][a_row + q*64][a_c4]);
            asm volatile("cp.async.cg.shared.global [%0], [%1], 16;" :: "r"(dst), "l"(src));
        }
        #pragma unroll
        for (int q = 0; q < 2; q++) {
            const float* src = &Bm[(size_t)(k0 + b_kr + q*8)*N + bcol + b_c4];
            unsigned dst = (unsigned)__cvta_generic_to_shared(&Bs[buf][b_kr + q*8][b_c4]);
            asm volatile("cp.async.cg.shared.global [%0], [%1], 16;" :: "r"(dst), "l"(src));
        }
        asm volatile("cp.async.commit_group;");
    };

    auto compute = [&](int buf) {
        #pragma unroll
        for (int ch = 0; ch < 2; ch++) {
            unsigned a[2][4];
            #pragma unroll
            for (int mi = 0; mi < 2; mi++) {
                int r0 = wr*32 + mi*16 + g;
                a[mi][0] = __float_as_uint(As[buf][r0    ][ch*8 + t4    ]);
                a[mi][1] = __float_as_uint(As[buf][r0 + 8][ch*8 + t4    ]);
                a[mi][2] = __float_as_uint(As[buf][r0    ][ch*8 + t4 + 4]);
                a[mi][3] = __float_as_uint(As[buf][r0 + 8][ch*8 + t4 + 4]);
            }
            #pragma unroll
            for (int ni = 0; ni < 8; ni++) {
                int col = wc*64 + ni*8 + g;
                unsigned b0 = __float_as_uint(Bs[buf][ch*8 + t4    ][col]);
                unsigned b1 = __float_as_uint(Bs[buf][ch*8 + t4 + 4][col]);
                #pragma unroll
                for (int mi = 0; mi < 2; mi++) {
                    asm volatile(
                        "mma.sync.aligned.m16n8k8.row.col.f32.tf32.tf32.f32 "
                        "{%0,%1,%2,%3},{%4,%5,%6,%7},{%8,%9},{%0,%1,%2,%3};"
                        : "+f"(acc[mi][ni][0]), "+f"(acc[mi][ni][1]),
                          "+f"(acc[mi][ni][2]), "+f"(acc[mi][ni][3])
                        : "r"(a[mi][0]), "r"(a[mi][1]), "r"(a[mi][2]), "r"(a[mi][3]),
                          "r"(b0), "r"(b1));
                }
            }
        }
    };

    const int nkt = K >> 4;
    issue(0, 0);
    for (int kt = 0; kt < nkt; kt++) {
        if (kt + 1 < nkt) {
            issue(kt + 1, (kt + 1) & 1);
            asm volatile("cp.async.wait_group 1;");
        } else {
            asm volatile("cp.async.wait_group 0;");
        }
        __syncthreads();        // tile kt visible to all threads
        compute(kt & 1);
        __syncthreads();        // all reads of buf kt&1 done before overwrite
    }

    // ---- epilogue ----
    #pragma unroll
    for (int mi = 0; mi < 2; mi++) {
        int r0 = brow + wr*32 + mi*16 + g;
        #pragma unroll
        for (int ni = 0; ni < 8; ni++) {
            int col = bcol + wc*64 + ni*8 + 2*t4;
            float v0 = acc[mi][ni][0];
            float v1 = acc[mi][ni][1];
            float v2 = acc[mi][ni][2];
            float v3 = acc[mi][ni][3];
            if (bias) {
                float bz0 = bias[col], bz1 = bias[col+1];
                v0 += bz0; v1 += bz1; v2 += bz0; v3 += bz1;
            }
            if (do_gelu) {
                v0 = 0.5f*v0*(1.f + erff(v0*0.70710678118654752f));
                v1 = 0.5f*v1*(1.f + erff(v1*0.70710678118654752f));
                v2 = 0.5f*v2*(1.f + erff(v2*0.70710678118654752f));
                v3 = 0.5f*v3*(1.f + erff(v3*0.70710678118654752f));
            }
            if (add) {
                float2 a0 = *(const float2*)&add[(size_t)r0*N + col];
                float2 a1 = *(const float2*)&add[(size_t)(r0+8)*N + col];
                v0 += a0.x; v1 += a0.y; v2 += a1.x; v3 += a1.y;
            }
            *(float2*)&C[(size_t)r0*N + col]     = make_float2(v0, v1);
            *(float2*)&C[(size_t)(r0+8)*N + col] = make_float2(v2, v3);
        }
    }
}

// ---------------- attention: one block per (b,h), thread i = query row ----------------
// Scores are tiny (|s| < 1 for these inputs): softmax computed without max
// subtraction (shift invariance; no overflow possible here).
#define ATTN_SMEM ((8192 + 8192 + 961) * 4)
__global__ __launch_bounds__(256)
void attn_kernel(const float* __restrict__ qkv, const float* __restrict__ bias_table,
                 float* __restrict__ o)
{
    extern __shared__ float sm[];
    float* ksh = sm;
    float* vsh = sm + 8192;
    float* bsh = sm + 16384;

    int b = blockIdx.x >> 3;
    int h = blockIdx.x & 7;
    int tid = threadIdx.x;

    const float* base = qkv + (size_t)b * HW_ * (3*INNER);

    for (int l = tid; l < 8192; l += 256) {
        int j = l >> 5, d = l & 31;
        ksh[l] = base[(size_t)j*(3*INNER) + INNER   + h*DHEAD + d];
        vsh[l] = base[(size_t)j*(3*INNER) + 2*INNER + h*DHEAD + d];
    }
    for (int l = tid; l < 961; l += 256) bsh[l] = bias_table[(size_t)l*HEADS + h];
    __syncthreads();

    const int i = tid;
    const float scale = 0.17677669529663688f;
    float4 qv[8];
    const float4* qp = (const float4*)(base + (size_t)i*(3*INNER) + h*DHEAD);
    #pragma unroll
    for (int dd = 0; dd < 8; dd++) {
        float4 q = qp[dd];
        qv[dd] = make_float4(q.x*scale, q.y*scale, q.z*scale, q.w*scale);
    }

    int yi = i >> 4, xi = i & 15;
    float lsum = 0.f;
    float acc[DHEAD];
    #pragma unroll
    for (int d = 0; d < DHEAD; d++) acc[d] = 0.f;

    const float* brow = bsh + (yi + 15)*31 + (xi + 15);
    for (int j = 0; j < HW_; j++) {
        const float4* kr = (const float4*)(ksh + j*DHEAD);
        float s0 = 0.f, s1 = 0.f, s2 = 0.f, s3 = 0.f;
        #pragma unroll
        for (int dd = 0; dd < 8; dd++) {
            float4 kv = kr[dd];
            s0 = fmaf(qv[dd].x, kv.x, s0);
            s1 = fmaf(qv[dd].y, kv.y, s1);
            s2 = fmaf(qv[dd].z, kv.z, s2);
            s3 = fmaf(qv[dd].w, kv.w, s3);
        }
        int yj = j >> 4, xj = j & 15;
        float s = (s0 + s1) + (s2 + s3) + brow[-(yj*31 + xj)];

        float p = __expf(s);
        lsum += p;
        const float4* vr = (const float4*)(vsh + j*DHEAD);
        #pragma unroll
        for (int dd = 0; dd < 8; dd++) {
            float4 vv = vr[dd];
            acc[dd*4+0] = fmaf(p, vv.x, acc[dd*4+0]);
            acc[dd*4+1] = fmaf(p, vv.y, acc[dd*4+1]);
            acc[dd*4+2] = fmaf(p, vv.z, acc[dd*4+2]);
            acc[dd*4+3] = fmaf(p, vv.w, acc[dd*4+3]);
        }
    }

    float inv = 1.f / lsum;
    float* op = o + ((size_t)(b*HW_ + i))*INNER + h*DHEAD;
    #pragma unroll
    for (int d = 0; d < DHEAD; d++) op[d] = acc[d] * inv;
}

// ---------------- output transpose: y[B,n,C] -> out[B,C,H,W] ----------------
__global__ void transpose_out_kernel(const float* __restrict__ y, float* __restrict__ out)
{
    __shared__ float tile[32][33];
    int b  = blockIdx.z;
    int c0 = blockIdx.x * 32;
    int p0 = blockIdx.y * 32;
    const float* yb = y  + (size_t)b * HW_ * C_;
    float*       ob = out + (size_t)b * C_ * HW_;

    for (int i = threadIdx.y; i < 32; i += 8)
        tile[i][threadIdx.x] = yb[(size_t)(p0 + i)*C_ + c0 + threadIdx.x];
    __syncthreads();
    for (int i = threadIdx.y; i < 32; i += 8)
        ob[(size_t)(c0 + i)*HW_ + p0 + threadIdx.x] = tile[threadIdx.x][i];
}

// ---------------- launch ----------------
extern "C" void kernel_launch(void* const* d_in, const int* in_sizes, int n_in,
                              void* d_out, int out_size)
{
    const float* x          = (const float*)d_in[0];
    const float* ln1_g      = (const float*)d_in[1];
    const float* ln1_b      = (const float*)d_in[2];
    const float* w_qkv      = (const float*)d_in[3];
    const float* bias_table = (const float*)d_in[4];
    const float* w_out      = (const float*)d_in[5];
    const float* b_out      = (const float*)d_in[6];
    const float* ln2_g      = (const float*)d_in[7];
    const float* ln2_b      = (const float*)d_in[8];
    const float* w_ff1      = (const float*)d_in[9];
    const float* b_ff1      = (const float*)d_in[10];
    const float* w_ff2      = (const float*)d_in[11];
    const float* b_ff2      = (const float*)d_in[12];

    float *t, *a, *f, *qkv, *o, *s1, *g;
    cudaGetSymbolAddress((void**)&t,   g_t);
    cudaGetSymbolAddress((void**)&a,   g_a);
    cudaGetSymbolAddress((void**)&f,   g_f);
    cudaGetSymbolAddress((void**)&qkv, g_qkv);
    cudaGetSymbolAddress((void**)&o,   g_o);
    cudaGetSymbolAddress((void**)&s1,  g_s1);
    cudaGetSymbolAddress((void**)&g,   g_g);

    cudaFuncSetAttribute(attn_kernel, cudaFuncAttributeMaxDynamicSharedMemorySize, ATTN_SMEM);

    // 1) transpose + LN1 + LN2
    ln_kernel<<<MTOT, 384>>>(x, ln1_g, ln1_b, ln2_g, ln2_b, t, a, f);

    // 2) qkv = a @ w_qkv
    tgemm_kernel<<<dim3(3*INNER/128, MTOT/128), 256>>>(a, w_qkv, qkv,
        MTOT, 3*INNER, C_, nullptr, nullptr, 0);

    // 3) attention
    attn_kernel<<<B_*HEADS, 256, ATTN_SMEM>>>(qkv, bias_table, o);

    // 4) s1 = t + (o @ w_out + b_out)
    tgemm_kernel<<<dim3(C_/128, MTOT/128), 256>>>(o, w_out, s1,
        MTOT, C_, INNER, b_out, t, 0);

    // 5) g = gelu(f @ w_ff1 + b_ff1)
    tgemm_kernel<<<dim3(HID/128, MTOT/128), 256>>>(f, w_ff1, g,
        MTOT, HID, C_, b_ff1, nullptr, 1);

    // 6) y = s1 + (g @ w_ff2 + b_ff2)
    tgemm_kernel<<<dim3(C_/128, MTOT/128), 256>>>(g, w_ff2, a,
        MTOT, C_, HID, b_ff2, s1, 0);

    // 7) out[B,C,H,W] = y transposed
    transpose_out_kernel<<<dim3(C_/32, HW_/32, B_), dim3(32, 8)>>>(a, (float*)d_out);
}

// round 5
// speedup vs baseline: 3.1214x; 1.2576x over previous
#include <cuda_runtime.h>
#include <cuda_fp16.h>
#include <math.h>

// ---------------- problem constants ----------------
#define B_   64
#define C_   384
#define HW_  256            // n = H*W
#define MTOT (B_*HW_)       // 16384
#define HEADS 8
#define DHEAD 32
#define INNER (HEADS*DHEAD) // 256
#define HID   (4*C_)        // 1536

// ---------------- device scratch (allocation-free rule) ----------------
__device__ float g_t  [MTOT*C_];
__device__ float g_a  [MTOT*C_];
__device__ float g_f  [MTOT*C_];
__device__ float g_qkv[MTOT*3*INNER];
__device__ float g_o  [MTOT*INNER];
__device__ float g_s1 [MTOT*C_];
__device__ float g_g  [MTOT*HID];

// ---------------- fused transpose + dual LayerNorm ----------------
__global__ void ln_kernel(const float* __restrict__ x,
                          const float* __restrict__ g1, const float* __restrict__ b1,
                          const float* __restrict__ g2, const float* __restrict__ b2,
                          float* __restrict__ t, float* __restrict__ a, float* __restrict__ f)
{
    int row = blockIdx.x;
    int b   = row >> 8;
    int p   = row & 255;
    int c   = threadIdx.x;

    float v = x[((size_t)b*C_ + c)*HW_ + p];

    __shared__ float red[12];
    __shared__ float s_mean, s_var;

    float s = v;
    #pragma unroll
    for (int o = 16; o; o >>= 1) s += __shfl_down_sync(0xffffffffu, s, o);
    if ((c & 31) == 0) red[c >> 5] = s;
    __syncthreads();
    if (c < 32) {
        float z = (c < 12) ? red[c] : 0.f;
        #pragma unroll
        for (int o = 16; o; o >>= 1) z += __shfl_down_sync(0xffffffffu, z, o);
        if (c == 0) s_mean = z * (1.f/384.f);
    }
    __syncthreads();
    float mean = s_mean;
    float d = v - mean;

    float sq = d*d;
    #pragma unroll
    for (int o = 16; o; o >>= 1) sq += __shfl_down_sync(0xffffffffu, sq, o);
    __syncthreads();
    if ((c & 31) == 0) red[c >> 5] = sq;
    __syncthreads();
    if (c < 32) {
        float z = (c < 12) ? red[c] : 0.f;
        #pragma unroll
        for (int o = 16; o; o >>= 1) z += __shfl_down_sync(0xffffffffu, z, o);
        if (c == 0) s_var = z * (1.f/384.f);
    }
    __syncthreads();
    float rstd = rsqrtf(s_var + 1e-5f);

    size_t oidx = (size_t)row*C_ + c;
    t[oidx] = v;
    float nrm = d * rstd;
    a[oidx] = nrm * g1[c] + b1[c];
    f[oidx] = nrm * g2[c] + b2[c];
}

// ---------------- tf32 tensor-core GEMM (unchanged from R4) ----------------
__global__ __launch_bounds__(256, 2)
void tgemm_kernel(const float* __restrict__ A, const float* __restrict__ Bm,
                  float* __restrict__ C, int M, int N, int K,
                  const float* __restrict__ bias, const float* __restrict__ add,
                  int do_gelu)
{
    __shared__ float As[2][128][20];
    __shared__ float Bs[2][16][136];

    const int tid  = threadIdx.x;
    const int warp = tid >> 5;
    const int lane = tid & 31;
    const int g    = lane >> 2;
    const int t4   = lane & 3;

    const int brow = blockIdx.y * 128;
    const int bcol = blockIdx.x * 128;

    const int wr = warp & 3;
    const int wc = warp >> 2;

    float acc[2][8][4];
    #pragma unroll
    for (int mi = 0; mi < 2; mi++)
        #pragma unroll
        for (int ni = 0; ni < 8; ni++)
            #pragma unroll
            for (int e = 0; e < 4; e++) acc[mi][ni][e] = 0.f;

    const int a_row = tid >> 2;
    const int a_c4  = (tid & 3) * 4;
    const int b_kr  = tid >> 5;
    const int b_c4  = (tid & 31) * 4;

    auto issue = [&](int kt, int buf) {
        int k0 = kt * 16;
        #pragma unroll
        for (int q = 0; q < 2; q++) {
            const float* src = &A[(size_t)(brow + a_row + q*64)*K + k0 + a_c4];
            unsigned dst = (unsigned)__cvta_generic_to_shared(&As[buf][a_row + q*64][a_c4]);
            asm volatile("cp.async.cg.shared.global [%0], [%1], 16;" :: "r"(dst), "l"(src));
        }
        #pragma unroll
        for (int q = 0; q < 2; q++) {
            const float* src = &Bm[(size_t)(k0 + b_kr + q*8)*N + bcol + b_c4];
            unsigned dst = (unsigned)__cvta_generic_to_shared(&Bs[buf][b_kr + q*8][b_c4]);
            asm volatile("cp.async.cg.shared.global [%0], [%1], 16;" :: "r"(dst), "l"(src));
        }
        asm volatile("cp.async.commit_group;");
    };

    auto compute = [&](int buf) {
        #pragma unroll
        for (int ch = 0; ch < 2; ch++) {
            unsigned a[2][4];
            #pragma unroll
            for (int mi = 0; mi < 2; mi++) {
                int r0 = wr*32 + mi*16 + g;
                a[mi][0] = __float_as_uint(As[buf][r0    ][ch*8 + t4    ]);
                a[mi][1] = __float_as_uint(As[buf][r0 + 8][ch*8 + t4    ]);
                a[mi][2] = __float_as_uint(As[buf][r0    ][ch*8 + t4 + 4]);
                a[mi][3] = __float_as_uint(As[buf][r0 + 8][ch*8 + t4 + 4]);
            }
            #pragma unroll
            for (int ni = 0; ni < 8; ni++) {
                int col = wc*64 + ni*8 + g;
                unsigned b0 = __float_as_uint(Bs[buf][ch*8 + t4    ][col]);
                unsigned b1 = __float_as_uint(Bs[buf][ch*8 + t4 + 4][col]);
                #pragma unroll
                for (int mi = 0; mi < 2; mi++) {
                    asm volatile(
                        "mma.sync.aligned.m16n8k8.row.col.f32.tf32.tf32.f32 "
                        "{%0,%1,%2,%3},{%4,%5,%6,%7},{%8,%9},{%0,%1,%2,%3};"
                        : "+f"(acc[mi][ni][0]), "+f"(acc[mi][ni][1]),
                          "+f"(acc[mi][ni][2]), "+f"(acc[mi][ni][3])
                        : "r"(a[mi][0]), "r"(a[mi][1]), "r"(a[mi][2]), "r"(a[mi][3]),
                          "r"(b0), "r"(b1));
                }
            }
        }
    };

    const int nkt = K >> 4;
    issue(0, 0);
    for (int kt = 0; kt < nkt; kt++) {
        if (kt + 1 < nkt) {
            issue(kt + 1, (kt + 1) & 1);
            asm volatile("cp.async.wait_group 1;");
        } else {
            asm volatile("cp.async.wait_group 0;");
        }
        __syncthreads();
        compute(kt & 1);
        __syncthreads();
    }

    #pragma unroll
    for (int mi = 0; mi < 2; mi++) {
        int r0 = brow + wr*32 + mi*16 + g;
        #pragma unroll
        for (int ni = 0; ni < 8; ni++) {
            int col = bcol + wc*64 + ni*8 + 2*t4;
            float v0 = acc[mi][ni][0];
            float v1 = acc[mi][ni][1];
            float v2 = acc[mi][ni][2];
            float v3 = acc[mi][ni][3];
            if (bias) {
                float bz0 = bias[col], bz1 = bias[col+1];
                v0 += bz0; v1 += bz1; v2 += bz0; v3 += bz1;
            }
            if (do_gelu) {
                v0 = 0.5f*v0*(1.f + erff(v0*0.70710678118654752f));
                v1 = 0.5f*v1*(1.f + erff(v1*0.70710678118654752f));
                v2 = 0.5f*v2*(1.f + erff(v2*0.70710678118654752f));
                v3 = 0.5f*v3*(1.f + erff(v3*0.70710678118654752f));
            }
            if (add) {
                float2 a0 = *(const float2*)&add[(size_t)r0*N + col];
                float2 a1 = *(const float2*)&add[(size_t)(r0+8)*N + col];
                v0 += a0.x; v1 += a0.y; v2 += a1.x; v3 += a1.y;
            }
            *(float2*)&C[(size_t)r0*N + col]     = make_float2(v0, v1);
            *(float2*)&C[(size_t)(r0+8)*N + col] = make_float2(v2, v3);
        }
    }
}

// ---------------- tensor-core attention: one CTA per (b,h) ----------------
// S = Q K^T (tf32 mma, K in smem pitch 36 -> conflict-free), P = exp(S+bias)
// packed straight from mma C-layout into m16n8k16 f16 A-fragments,
// O += P V (fp16 mma, V^T in smem fp16 pitch 264 -> conflict-free).
// Softmax without max subtraction (scores are tiny for these inputs; verified
// rounds 3-4).
#define ATT_KS_F   (256*36)            // K tile, fp32, pitch 36
#define ATT_VS_H   (32*264)            // V^T tile, fp16, pitch 264
#define ATT_SMEM_B (ATT_KS_F*4 + ATT_VS_H*2 + 961*4)

__global__ void attn_mma_kernel(const float* __restrict__ qkv,
                                const float* __restrict__ bias_table,
                                float* __restrict__ o)
{
    extern __shared__ float sm[];
    float*  ks  = sm;                              // [256][36]
    __half* vs  = (__half*)(sm + ATT_KS_F);        // [32][264]
    float*  bsh = sm + ATT_KS_F + ATT_VS_H/2;      // [961]

    const int b = blockIdx.x >> 3, h = blockIdx.x & 7;
    const int tid = threadIdx.x, warp = tid >> 5, lane = tid & 31;
    const int g = lane >> 2, t4 = lane & 3;
    const float* base = qkv + (size_t)b * HW_ * 768;

    // stage K (fp32) and V (fp16, transposed)
    for (int l = tid; l < 2048; l += 256) {
        int j = l >> 3, c4 = (l & 7) * 4;
        float4 kv = *(const float4*)&base[(size_t)j*768 + 256 + h*32 + c4];
        *(float4*)&ks[j*36 + c4] = kv;
        float4 vv = *(const float4*)&base[(size_t)j*768 + 512 + h*32 + c4];
        vs[(c4+0)*264 + j] = __float2half(vv.x);
        vs[(c4+1)*264 + j] = __float2half(vv.y);
        vs[(c4+2)*264 + j] = __float2half(vv.z);
        vs[(c4+3)*264 + j] = __float2half(vv.w);
    }
    for (int l = tid; l < 961; l += 256) bsh[l] = bias_table[(size_t)l*8 + h];

    // Q fragments in registers (scaled); warp owns rows warp*32..+32
    const float scale = 0.17677669529663688f;
    unsigned qa[2][4][4];
    #pragma unroll
    for (int mi = 0; mi < 2; mi++) {
        int r0 = warp*32 + mi*16 + g;
        const float* q0 = &base[(size_t)r0*768 + h*32];
        const float* q1 = &base[(size_t)(r0+8)*768 + h*32];
        #pragma unroll
        for (int k = 0; k < 4; k++) {
            qa[mi][k][0] = __float_as_uint(q0[k*8 + t4]     * scale);
            qa[mi][k][1] = __float_as_uint(q1[k*8 + t4]     * scale);
            qa[mi][k][2] = __float_as_uint(q0[k*8 + t4 + 4] * scale);
            qa[mi][k][3] = __float_as_uint(q1[k*8 + t4 + 4] * scale);
        }
    }

    // per-row bias bases: bias(i,j) = bsh[bb - ((j>>4)*31 + (j&15))]
    int bb[2][2];
    #pragma unroll
    for (int mi = 0; mi < 2; mi++) {
        int i0 = warp*32 + mi*16 + g;
        bb[mi][0] = ((i0 >> 4) + 15)*31 + (i0 & 15) + 15;
        bb[mi][1] = (((i0+8) >> 4) + 15)*31 + ((i0+8) & 15) + 15;
    }
    __syncthreads();

    float acco[2][4][4];
    #pragma unroll
    for (int mi = 0; mi < 2; mi++)
        #pragma unroll
        for (int vn = 0; vn < 4; vn++)
            #pragma unroll
            for (int e = 0; e < 4; e++) acco[mi][vn][e] = 0.f;
    float rs[2][2] = {{0.f, 0.f}, {0.f, 0.f}};

    for (int j0 = 0; j0 < 256; j0 += 32) {
        // ---- S = Q K^T chunk [32 rows x 32 cols] per warp ----
        float accs[2][4][4];
        #pragma unroll
        for (int mi = 0; mi < 2; mi++)
            #pragma unroll
            for (int ni = 0; ni < 4; ni++)
                #pragma unroll
                for (int e = 0; e < 4; e++) accs[mi][ni][e] = 0.f;

        #pragma unroll
        for (int k = 0; k < 4; k++) {
            #pragma unroll
            for (int ni = 0; ni < 4; ni++) {
                unsigned kb0 = __float_as_uint(ks[(j0 + ni*8 + g)*36 + k*8 + t4]);
                unsigned kb1 = __float_as_uint(ks[(j0 + ni*8 + g)*36 + k*8 + t4 + 4]);
                #pragma unroll
                for (int mi = 0; mi < 2; mi++) {
                    asm volatile(
                        "mma.sync.aligned.m16n8k8.row.col.f32.tf32.tf32.f32 "
                        "{%0,%1,%2,%3},{%4,%5,%6,%7},{%8,%9},{%0,%1,%2,%3};"
                        : "+f"(accs[mi][ni][0]), "+f"(accs[mi][ni][1]),
                          "+f"(accs[mi][ni][2]), "+f"(accs[mi][ni][3])
                        : "r"(qa[mi][k][0]), "r"(qa[mi][k][1]),
                          "r"(qa[mi][k][2]), "r"(qa[mi][k][3]),
                          "r"(kb0), "r"(kb1));
                }
            }
        }

        // ---- P = exp(S + bias), rowsum, pack to fp16 A-fragments ----
        unsigned pk[2][4][2];
        #pragma unroll
        for (int mi = 0; mi < 2; mi++) {
            #pragma unroll
            for (int ni = 0; ni < 4; ni++) {
                int j  = j0 + ni*8 + 2*t4;
                int o0 = (j >> 4)*31 + (j & 15);
                int o1 = ((j+1) >> 4)*31 + ((j+1) & 15);
                float p0 = __expf(accs[mi][ni][0] + bsh[bb[mi][0] - o0]);
                float p1 = __expf(accs[mi][ni][1] + bsh[bb[mi][0] - o1]);
                float p2 = __expf(accs[mi][ni][2] + bsh[bb[mi][1] - o0]);
                float p3 = __expf(accs[mi][ni][3] + bsh[bb[mi][1] - o1]);
                rs[mi][0] += p0 + p1;
                rs[mi][1] += p2 + p3;
                __half2 h01 = __floats2half2_rn(p0, p1);
                __half2 h23 = __floats2half2_rn(p2, p3);
                pk[mi][ni][0] = *(unsigned*)&h01;
                pk[mi][ni][1] = *(unsigned*)&h23;
            }
        }

        // ---- O += P V  (m16n8k16 fp16) ----
        #pragma unroll
        for (int k = 0; k < 2; k++) {
            #pragma unroll
            for (int vn = 0; vn < 4; vn++) {
                unsigned vb0 = *(const unsigned*)&vs[(vn*8 + g)*264 + j0 + k*16 + 2*t4];
                unsigned vb1 = *(const unsigned*)&vs[(vn*8 + g)*264 + j0 + k*16 + 2*t4 + 8];
                #pragma unroll
                for (int mi = 0; mi < 2; mi++) {
                    asm volatile(
                        "mma.sync.aligned.m16n8k16.row.col.f32.f16.f16.f32 "
                        "{%0,%1,%2,%3},{%4,%5,%6,%7},{%8,%9},{%0,%1,%2,%3};"
                        : "+f"(acco[mi][vn][0]), "+f"(acco[mi][vn][1]),
                          "+f"(acco[mi][vn][2]), "+f"(acco[mi][vn][3])
                        : "r"(pk[mi][2*k][0]), "r"(pk[mi][2*k][1]),
                          "r"(pk[mi][2*k+1][0]), "r"(pk[mi][2*k+1][1]),
                          "r"(vb0), "r"(vb1));
                }
            }
        }
    }

    // rowsum reduce across quad (lanes sharing g), invert
    #pragma unroll
    for (int mi = 0; mi < 2; mi++)
        #pragma unroll
        for (int r = 0; r < 2; r++) {
            float v = rs[mi][r];
            v += __shfl_xor_sync(0xffffffffu, v, 1);
            v += __shfl_xor_sync(0xffffffffu, v, 2);
            rs[mi][r] = 1.f / v;
        }

    // write O
    #pragma unroll
    for (int mi = 0; mi < 2; mi++) {
        int r0 = warp*32 + mi*16 + g;
        #pragma unroll
        for (int vn = 0; vn < 4; vn++) {
            int col = h*32 + vn*8 + 2*t4;
            *(float2*)&o[((size_t)(b*HW_) + r0)*INNER + col] =
                make_float2(acco[mi][vn][0]*rs[mi][0], acco[mi][vn][1]*rs[mi][0]);
            *(float2*)&o[((size_t)(b*HW_) + r0 + 8)*INNER + col] =
                make_float2(acco[mi][vn][2]*rs[mi][1], acco[mi][vn][3]*rs[mi][1]);
        }
    }
}

// ---------------- output transpose: y[B,n,C] -> out[B,C,H,W] ----------------
__global__ void transpose_out_kernel(const float* __restrict__ y, float* __restrict__ out)
{
    __shared__ float tile[32][33];
    int b  = blockIdx.z;
    int c0 = blockIdx.x * 32;
    int p0 = blockIdx.y * 32;
    const float* yb = y  + (size_t)b * HW_ * C_;
    float*       ob = out + (size_t)b * C_ * HW_;

    for (int i = threadIdx.y; i < 32; i += 8)
        tile[i][threadIdx.x] = yb[(size_t)(p0 + i)*C_ + c0 + threadIdx.x];
    __syncthreads();
    for (int i = threadIdx.y; i < 32; i += 8)
        ob[(size_t)(c0 + i)*HW_ + p0 + threadIdx.x] = tile[threadIdx.x][i];
}

// ---------------- launch ----------------
extern "C" void kernel_launch(void* const* d_in, const int* in_sizes, int n_in,
                              void* d_out, int out_size)
{
    const float* x          = (const float*)d_in[0];
    const float* ln1_g      = (const float*)d_in[1];
    const float* ln1_b      = (const float*)d_in[2];
    const float* w_qkv      = (const float*)d_in[3];
    const float* bias_table = (const float*)d_in[4];
    const float* w_out      = (const float*)d_in[5];
    const float* b_out      = (const float*)d_in[6];
    const float* ln2_g      = (const float*)d_in[7];
    const float* ln2_b      = (const float*)d_in[8];
    const float* w_ff1      = (const float*)d_in[9];
    const float* b_ff1      = (const float*)d_in[10];
    const float* w_ff2      = (const float*)d_in[11];
    const float* b_ff2      = (const float*)d_in[12];

    float *t, *a, *f, *qkv, *o, *s1, *g;
    cudaGetSymbolAddress((void**)&t,   g_t);
    cudaGetSymbolAddress((void**)&a,   g_a);
    cudaGetSymbolAddress((void**)&f,   g_f);
    cudaGetSymbolAddress((void**)&qkv, g_qkv);
    cudaGetSymbolAddress((void**)&o,   g_o);
    cudaGetSymbolAddress((void**)&s1,  g_s1);
    cudaGetSymbolAddress((void**)&g,   g_g);

    cudaFuncSetAttribute(attn_mma_kernel, cudaFuncAttributeMaxDynamicSharedMemorySize, ATT_SMEM_B);

    // 1) transpose + LN1 + LN2
    ln_kernel<<<MTOT, 384>>>(x, ln1_g, ln1_b, ln2_g, ln2_b, t, a, f);

    // 2) qkv = a @ w_qkv
    tgemm_kernel<<<dim3(3*INNER/128, MTOT/128), 256>>>(a, w_qkv, qkv,
        MTOT, 3*INNER, C_, nullptr, nullptr, 0);

    // 3) attention (tensor core)
    attn_mma_kernel<<<B_*HEADS, 256, ATT_SMEM_B>>>(qkv, bias_table, o);

    // 4) s1 = t + (o @ w_out + b_out)
    tgemm_kernel<<<dim3(C_/128, MTOT/128), 256>>>(o, w_out, s1,
        MTOT, C_, INNER, b_out, t, 0);

    // 5) g = gelu(f @ w_ff1 + b_ff1)
    tgemm_kernel<<<dim3(HID/128, MTOT/128), 256>>>(f, w_ff1, g,
        MTOT, HID, C_, b_ff1, nullptr, 1);

    // 6) y = s1 + (g @ w_ff2 + b_ff2)
    tgemm_kernel<<<dim3(C_/128, MTOT/128), 256>>>(g, w_ff2, a,
        MTOT, C_, HID, b_ff2, s1, 0);

    // 7) out[B,C,H,W] = y transposed
    transpose_out_kernel<<<dim3(C_/32, HW_/32, B_), dim3(32, 8)>>>(a, (float*)d_out);
}

// round 6
// speedup vs baseline: 3.5186x; 1.1273x over previous
#include <cuda_runtime.h>
#include <cuda_fp16.h>
#include <math.h>

// ---------------- problem constants ----------------
#define B_   64
#define C_   384
#define HW_  256            // n = H*W
#define MTOT (B_*HW_)       // 16384
#define HEADS 8
#define DHEAD 32
#define INNER (HEADS*DHEAD) // 256
#define HID   (4*C_)        // 1536

// ---------------- device scratch (allocation-free rule) ----------------
__device__ float g_t  [MTOT*C_];
__device__ float g_a  [MTOT*C_];
__device__ float g_f  [MTOT*C_];
__device__ float g_qkv[MTOT*3*INNER];
__device__ float g_o  [MTOT*INNER];
__device__ float g_s1 [MTOT*C_];
__device__ float g_ff [MTOT*C_];
__device__ float g_g  [MTOT*HID];

// ---------------- fused transpose + dual LayerNorm ----------------
__global__ void ln_kernel(const float* __restrict__ x,
                          const float* __restrict__ g1, const float* __restrict__ b1,
                          const float* __restrict__ g2, const float* __restrict__ b2,
                          float* __restrict__ t, float* __restrict__ a, float* __restrict__ f)
{
    int row = blockIdx.x;
    int b   = row >> 8;
    int p   = row & 255;
    int c   = threadIdx.x;

    float v = x[((size_t)b*C_ + c)*HW_ + p];

    __shared__ float red[12];
    __shared__ float s_mean, s_var;

    float s = v;
    #pragma unroll
    for (int o = 16; o; o >>= 1) s += __shfl_down_sync(0xffffffffu, s, o);
    if ((c & 31) == 0) red[c >> 5] = s;
    __syncthreads();
    if (c < 32) {
        float z = (c < 12) ? red[c] : 0.f;
        #pragma unroll
        for (int o = 16; o; o >>= 1) z += __shfl_down_sync(0xffffffffu, z, o);
        if (c == 0) s_mean = z * (1.f/384.f);
    }
    __syncthreads();
    float mean = s_mean;
    float d = v - mean;

    float sq = d*d;
    #pragma unroll
    for (int o = 16; o; o >>= 1) sq += __shfl_down_sync(0xffffffffu, sq, o);
    __syncthreads();
    if ((c & 31) == 0) red[c >> 5] = sq;
    __syncthreads();
    if (c < 32) {
        float z = (c < 12) ? red[c] : 0.f;
        #pragma unroll
        for (int o = 16; o; o >>= 1) z += __shfl_down_sync(0xffffffffu, z, o);
        if (c == 0) s_var = z * (1.f/384.f);
    }
    __syncthreads();
    float rstd = rsqrtf(s_var + 1e-5f);

    size_t oidx = (size_t)row*C_ + c;
    t[oidx] = v;
    float nrm = d * rstd;
    a[oidx] = nrm * g1[c] + b1[c];
    f[oidx] = nrm * g2[c] + b2[c];
}

// ---------------- tf32 tensor-core GEMM (unchanged from R4) ----------------
__global__ __launch_bounds__(256, 2)
void tgemm_kernel(const float* __restrict__ A, const float* __restrict__ Bm,
                  float* __restrict__ C, int M, int N, int K,
                  const float* __restrict__ bias, const float* __restrict__ add,
                  int do_gelu)
{
    __shared__ float As[2][128][20];
    __shared__ float Bs[2][16][136];

    const int tid  = threadIdx.x;
    const int warp = tid >> 5;
    const int lane = tid & 31;
    const int g    = lane >> 2;
    const int t4   = lane & 3;

    const int brow = blockIdx.y * 128;
    const int bcol = blockIdx.x * 128;

    const int wr = warp & 3;
    const int wc = warp >> 2;

    float acc[2][8][4];
    #pragma unroll
    for (int mi = 0; mi < 2; mi++)
        #pragma unroll
        for (int ni = 0; ni < 8; ni++)
            #pragma unroll
            for (int e = 0; e < 4; e++) acc[mi][ni][e] = 0.f;

    const int a_row = tid >> 2;
    const int a_c4  = (tid & 3) * 4;
    const int b_kr  = tid >> 5;
    const int b_c4  = (tid & 31) * 4;

    auto issue = [&](int kt, int buf) {
        int k0 = kt * 16;
        #pragma unroll
        for (int q = 0; q < 2; q++) {
            const float* src = &A[(size_t)(brow + a_row + q*64)*K + k0 + a_c4];
            unsigned dst = (unsigned)__cvta_generic_to_shared(&As[buf][a_row + q*64][a_c4]);
            asm volatile("cp.async.cg.shared.global [%0], [%1], 16;" :: "r"(dst), "l"(src));
        }
        #pragma unroll
        for (int q = 0; q < 2; q++) {
            const float* src = &Bm[(size_t)(k0 + b_kr + q*8)*N + bcol + b_c4];
            unsigned dst = (unsigned)__cvta_generic_to_shared(&Bs[buf][b_kr + q*8][b_c4]);
            asm volatile("cp.async.cg.shared.global [%0], [%1], 16;" :: "r"(dst), "l"(src));
        }
        asm volatile("cp.async.commit_group;");
    };

    auto compute = [&](int buf) {
        #pragma unroll
        for (int ch = 0; ch < 2; ch++) {
            unsigned a[2][4];
            #pragma unroll
            for (int mi = 0; mi < 2; mi++) {
                int r0 = wr*32 + mi*16 + g;
                a[mi][0] = __float_as_uint(As[buf][r0    ][ch*8 + t4    ]);
                a[mi][1] = __float_as_uint(As[buf][r0 + 8][ch*8 + t4    ]);
                a[mi][2] = __float_as_uint(As[buf][r0    ][ch*8 + t4 + 4]);
                a[mi][3] = __float_as_uint(As[buf][r0 + 8][ch*8 + t4 + 4]);
            }
            #pragma unroll
            for (int ni = 0; ni < 8; ni++) {
                int col = wc*64 + ni*8 + g;
                unsigned b0 = __float_as_uint(Bs[buf][ch*8 + t4    ][col]);
                unsigned b1 = __float_as_uint(Bs[buf][ch*8 + t4 + 4][col]);
                #pragma unroll
                for (int mi = 0; mi < 2; mi++) {
                    asm volatile(
                        "mma.sync.aligned.m16n8k8.row.col.f32.tf32.tf32.f32 "
                        "{%0,%1,%2,%3},{%4,%5,%6,%7},{%8,%9},{%0,%1,%2,%3};"
                        : "+f"(acc[mi][ni][0]), "+f"(acc[mi][ni][1]),
                          "+f"(acc[mi][ni][2]), "+f"(acc[mi][ni][3])
                        : "r"(a[mi][0]), "r"(a[mi][1]), "r"(a[mi][2]), "r"(a[mi][3]),
                          "r"(b0), "r"(b1));
                }
            }
        }
    };

    const int nkt = K >> 4;
    issue(0, 0);
    for (int kt = 0; kt < nkt; kt++) {
        if (kt + 1 < nkt) {
            issue(kt + 1, (kt + 1) & 1);
            asm volatile("cp.async.wait_group 1;");
        } else {
            asm volatile("cp.async.wait_group 0;");
        }
        __syncthreads();
        compute(kt & 1);
        __syncthreads();
    }

    #pragma unroll
    for (int mi = 0; mi < 2; mi++) {
        int r0 = brow + wr*32 + mi*16 + g;
        #pragma unroll
        for (int ni = 0; ni < 8; ni++) {
            int col = bcol + wc*64 + ni*8 + 2*t4;
            float v0 = acc[mi][ni][0];
            float v1 = acc[mi][ni][1];
            float v2 = acc[mi][ni][2];
            float v3 = acc[mi][ni][3];
            if (bias) {
                float bz0 = bias[col], bz1 = bias[col+1];
                v0 += bz0; v1 += bz1; v2 += bz0; v3 += bz1;
            }
            if (do_gelu) {
                v0 = 0.5f*v0*(1.f + erff(v0*0.70710678118654752f));
                v1 = 0.5f*v1*(1.f + erff(v1*0.70710678118654752f));
                v2 = 0.5f*v2*(1.f + erff(v2*0.70710678118654752f));
                v3 = 0.5f*v3*(1.f + erff(v3*0.70710678118654752f));
            }
            if (add) {
                float2 a0 = *(const float2*)&add[(size_t)r0*N + col];
                float2 a1 = *(const float2*)&add[(size_t)(r0+8)*N + col];
                v0 += a0.x; v1 += a0.y; v2 += a1.x; v3 += a1.y;
            }
            *(float2*)&C[(size_t)r0*N + col]     = make_float2(v0, v1);
            *(float2*)&C[(size_t)(r0+8)*N + col] = make_float2(v2, v3);
        }
    }
}

// ---------------- tensor-core attention (unchanged from R5) ----------------
#define ATT_KS_F   (256*36)
#define ATT_VS_H   (32*264)
#define ATT_SMEM_B (ATT_KS_F*4 + ATT_VS_H*2 + 961*4)

__global__ void attn_mma_kernel(const float* __restrict__ qkv,
                                const float* __restrict__ bias_table,
                                float* __restrict__ o)
{
    extern __shared__ float sm[];
    float*  ks  = sm;
    __half* vs  = (__half*)(sm + ATT_KS_F);
    float*  bsh = sm + ATT_KS_F + ATT_VS_H/2;

    const int b = blockIdx.x >> 3, h = blockIdx.x & 7;
    const int tid = threadIdx.x, warp = tid >> 5, lane = tid & 31;
    const int g = lane >> 2, t4 = lane & 3;
    const float* base = qkv + (size_t)b * HW_ * 768;

    for (int l = tid; l < 2048; l += 256) {
        int j = l >> 3, c4 = (l & 7) * 4;
        float4 kv = *(const float4*)&base[(size_t)j*768 + 256 + h*32 + c4];
        *(float4*)&ks[j*36 + c4] = kv;
        float4 vv = *(const float4*)&base[(size_t)j*768 + 512 + h*32 + c4];
        vs[(c4+0)*264 + j] = __float2half(vv.x);
        vs[(c4+1)*264 + j] = __float2half(vv.y);
        vs[(c4+2)*264 + j] = __float2half(vv.z);
        vs[(c4+3)*264 + j] = __float2half(vv.w);
    }
    for (int l = tid; l < 961; l += 256) bsh[l] = bias_table[(size_t)l*8 + h];

    const float scale = 0.17677669529663688f;
    unsigned qa[2][4][4];
    #pragma unroll
    for (int mi = 0; mi < 2; mi++) {
        int r0 = warp*32 + mi*16 + g;
        const float* q0 = &base[(size_t)r0*768 + h*32];
        const float* q1 = &base[(size_t)(r0+8)*768 + h*32];
        #pragma unroll
        for (int k = 0; k < 4; k++) {
            qa[mi][k][0] = __float_as_uint(q0[k*8 + t4]     * scale);
            qa[mi][k][1] = __float_as_uint(q1[k*8 + t4]     * scale);
            qa[mi][k][2] = __float_as_uint(q0[k*8 + t4 + 4] * scale);
            qa[mi][k][3] = __float_as_uint(q1[k*8 + t4 + 4] * scale);
        }
    }

    int bb[2][2];
    #pragma unroll
    for (int mi = 0; mi < 2; mi++) {
        int i0 = warp*32 + mi*16 + g;
        bb[mi][0] = ((i0 >> 4) + 15)*31 + (i0 & 15) + 15;
        bb[mi][1] = (((i0+8) >> 4) + 15)*31 + ((i0+8) & 15) + 15;
    }
    __syncthreads();

    float acco[2][4][4];
    #pragma unroll
    for (int mi = 0; mi < 2; mi++)
        #pragma unroll
        for (int vn = 0; vn < 4; vn++)
            #pragma unroll
            for (int e = 0; e < 4; e++) acco[mi][vn][e] = 0.f;
    float rs[2][2] = {{0.f, 0.f}, {0.f, 0.f}};

    for (int j0 = 0; j0 < 256; j0 += 32) {
        float accs[2][4][4];
        #pragma unroll
        for (int mi = 0; mi < 2; mi++)
            #pragma unroll
            for (int ni = 0; ni < 4; ni++)
                #pragma unroll
                for (int e = 0; e < 4; e++) accs[mi][ni][e] = 0.f;

        #pragma unroll
        for (int k = 0; k < 4; k++) {
            #pragma unroll
            for (int ni = 0; ni < 4; ni++) {
                unsigned kb0 = __float_as_uint(ks[(j0 + ni*8 + g)*36 + k*8 + t4]);
                unsigned kb1 = __float_as_uint(ks[(j0 + ni*8 + g)*36 + k*8 + t4 + 4]);
                #pragma unroll
                for (int mi = 0; mi < 2; mi++) {
                    asm volatile(
                        "mma.sync.aligned.m16n8k8.row.col.f32.tf32.tf32.f32 "
                        "{%0,%1,%2,%3},{%4,%5,%6,%7},{%8,%9},{%0,%1,%2,%3};"
                        : "+f"(accs[mi][ni][0]), "+f"(accs[mi][ni][1]),
                          "+f"(accs[mi][ni][2]), "+f"(accs[mi][ni][3])
                        : "r"(qa[mi][k][0]), "r"(qa[mi][k][1]),
                          "r"(qa[mi][k][2]), "r"(qa[mi][k][3]),
                          "r"(kb0), "r"(kb1));
                }
            }
        }

        unsigned pk[2][4][2];
        #pragma unroll
        for (int mi = 0; mi < 2; mi++) {
            #pragma unroll
            for (int ni = 0; ni < 4; ni++) {
                int j  = j0 + ni*8 + 2*t4;
                int o0 = (j >> 4)*31 + (j & 15);
                int o1 = ((j+1) >> 4)*31 + ((j+1) & 15);
                float p0 = __expf(accs[mi][ni][0] + bsh[bb[mi][0] - o0]);
                float p1 = __expf(accs[mi][ni][1] + bsh[bb[mi][0] - o1]);
                float p2 = __expf(accs[mi][ni][2] + bsh[bb[mi][1] - o0]);
                float p3 = __expf(accs[mi][ni][3] + bsh[bb[mi][1] - o1]);
                rs[mi][0] += p0 + p1;
                rs[mi][1] += p2 + p3;
                __half2 h01 = __floats2half2_rn(p0, p1);
                __half2 h23 = __floats2half2_rn(p2, p3);
                pk[mi][ni][0] = *(unsigned*)&h01;
                pk[mi][ni][1] = *(unsigned*)&h23;
            }
        }

        #pragma unroll
        for (int k = 0; k < 2; k++) {
            #pragma unroll
            for (int vn = 0; vn < 4; vn++) {
                unsigned vb0 = *(const unsigned*)&vs[(vn*8 + g)*264 + j0 + k*16 + 2*t4];
                unsigned vb1 = *(const unsigned*)&vs[(vn*8 + g)*264 + j0 + k*16 + 2*t4 + 8];
                #pragma unroll
                for (int mi = 0; mi < 2; mi++) {
                    asm volatile(
                        "mma.sync.aligned.m16n8k16.row.col.f32.f16.f16.f32 "
                        "{%0,%1,%2,%3},{%4,%5,%6,%7},{%8,%9},{%0,%1,%2,%3};"
                        : "+f"(acco[mi][vn][0]), "+f"(acco[mi][vn][1]),
                          "+f"(acco[mi][vn][2]), "+f"(acco[mi][vn][3])
                        : "r"(pk[mi][2*k][0]), "r"(pk[mi][2*k][1]),
                          "r"(pk[mi][2*k+1][0]), "r"(pk[mi][2*k+1][1]),
                          "r"(vb0), "r"(vb1));
                }
            }
        }
    }

    #pragma unroll
    for (int mi = 0; mi < 2; mi++)
        #pragma unroll
        for (int r = 0; r < 2; r++) {
            float v = rs[mi][r];
            v += __shfl_xor_sync(0xffffffffu, v, 1);
            v += __shfl_xor_sync(0xffffffffu, v, 2);
            rs[mi][r] = 1.f / v;
        }

    #pragma unroll
    for (int mi = 0; mi < 2; mi++) {
        int r0 = warp*32 + mi*16 + g;
        #pragma unroll
        for (int vn = 0; vn < 4; vn++) {
            int col = h*32 + vn*8 + 2*t4;
            *(float2*)&o[((size_t)(b*HW_) + r0)*INNER + col] =
                make_float2(acco[mi][vn][0]*rs[mi][0], acco[mi][vn][1]*rs[mi][0]);
            *(float2*)&o[((size_t)(b*HW_) + r0 + 8)*INNER + col] =
                make_float2(acco[mi][vn][2]*rs[mi][1], acco[mi][vn][3]*rs[mi][1]);
        }
    }
}

// ---------------- fused join: out[B,C,H,W] = transpose(s1 + ff) ----------------
__global__ void transpose_add_kernel(const float* __restrict__ s1,
                                     const float* __restrict__ ff,
                                     float* __restrict__ out)
{
    __shared__ float tile[32][33];
    int b  = blockIdx.z;
    int c0 = blockIdx.x * 32;
    int p0 = blockIdx.y * 32;

    for (int i = threadIdx.y; i < 32; i += 8) {
        size_t idx = (size_t)(b*HW_ + p0 + i)*C_ + c0 + threadIdx.x;
        tile[i][threadIdx.x] = s1[idx] + ff[idx];
    }
    __syncthreads();
    float* ob = out + (size_t)b * C_ * HW_;
    for (int i = threadIdx.y; i < 32; i += 8)
        ob[(size_t)(c0 + i)*HW_ + p0 + threadIdx.x] = tile[threadIdx.x][i];
}

// ---------------- launch ----------------
extern "C" void kernel_launch(void* const* d_in, const int* in_sizes, int n_in,
                              void* d_out, int out_size)
{
    const float* x          = (const float*)d_in[0];
    const float* ln1_g      = (const float*)d_in[1];
    const float* ln1_b      = (const float*)d_in[2];
    const float* w_qkv      = (const float*)d_in[3];
    const float* bias_table = (const float*)d_in[4];
    const float* w_out      = (const float*)d_in[5];
    const float* b_out      = (const float*)d_in[6];
    const float* ln2_g      = (const float*)d_in[7];
    const float* ln2_b      = (const float*)d_in[8];
    const float* w_ff1      = (const float*)d_in[9];
    const float* b_ff1      = (const float*)d_in[10];
    const float* w_ff2      = (const float*)d_in[11];
    const float* b_ff2      = (const float*)d_in[12];

    float *t, *a, *f, *qkv, *o, *s1, *ff, *g;
    cudaGetSymbolAddress((void**)&t,   g_t);
    cudaGetSymbolAddress((void**)&a,   g_a);
    cudaGetSymbolAddress((void**)&f,   g_f);
    cudaGetSymbolAddress((void**)&qkv, g_qkv);
    cudaGetSymbolAddress((void**)&o,   g_o);
    cudaGetSymbolAddress((void**)&s1,  g_s1);
    cudaGetSymbolAddress((void**)&ff,  g_ff);
    cudaGetSymbolAddress((void**)&g,   g_g);

    cudaFuncSetAttribute(attn_mma_kernel, cudaFuncAttributeMaxDynamicSharedMemorySize, ATT_SMEM_B);

    // one-time side-stream + events for graph fork/join
    static cudaStream_t s2 = nullptr;
    static cudaEvent_t evFork = nullptr, evJoin = nullptr;
    if (!s2) {
        cudaStreamCreateWithFlags(&s2, cudaStreamNonBlocking);
        cudaEventCreateWithFlags(&evFork, cudaEventDisableTiming);
        cudaEventCreateWithFlags(&evJoin, cudaEventDisableTiming);
    }

    // 1) transpose + LN1 + LN2 (main stream)
    ln_kernel<<<MTOT, 384>>>(x, ln1_g, ln1_b, ln2_g, ln2_b, t, a, f);

    // fork: FF branch on s2 (depends only on f)
    cudaEventRecord(evFork, 0);
    cudaStreamWaitEvent(s2, evFork, 0);

    // FF branch: g = gelu(f @ w_ff1 + b_ff1); ff = g @ w_ff2 + b_ff2
    tgemm_kernel<<<dim3(HID/128, MTOT/128), 256, 0, s2>>>(f, w_ff1, g,
        MTOT, HID, C_, b_ff1, nullptr, 1);
    tgemm_kernel<<<dim3(C_/128, MTOT/128), 256, 0, s2>>>(g, w_ff2, ff,
        MTOT, C_, HID, b_ff2, nullptr, 0);
    cudaEventRecord(evJoin, s2);

    // Attention branch (main stream)
    tgemm_kernel<<<dim3(3*INNER/128, MTOT/128), 256>>>(a, w_qkv, qkv,
        MTOT, 3*INNER, C_, nullptr, nullptr, 0);
    attn_mma_kernel<<<B_*HEADS, 256, ATT_SMEM_B>>>(qkv, bias_table, o);
    tgemm_kernel<<<dim3(C_/128, MTOT/128), 256>>>(o, w_out, s1,
        MTOT, C_, INNER, b_out, t, 0);

    // join, then fused add + transpose
    cudaStreamWaitEvent(0, evJoin, 0);
    transpose_add_kernel<<<dim3(C_/32, HW_/32, B_), dim3(32, 8)>>>(s1, ff, (float*)d_out);
}